// round 1
// baseline (speedup 1.0000x reference)
#include <cuda_runtime.h>
#include <cuda_bf16.h>
#include <math.h>

// Problem constants (fixed by the dataset)
#define PP   256          // para_code dim
#define FF   20           // feature channels == depth
#define HH   18
#define WW   18
#define HW   (HH*WW)      // 324
#define VOL  (FF*HH*WW)   // 6480
#define MAXB 4096
#define ROWS 16           // batch rows per block in the param kernel
#define PI_F 3.14159f

// Scratch for per-(b,f) affine params: c, s, scale, tx, ty  (stride 5)
__device__ float g_params[MAXB * FF * 5];

// ---------------------------------------------------------------------------
// Kernel 1: h = relu(pc @ W1 + b1); then scale/angle/trans projections.
// 16 batch rows per block, 256 threads, 4x4 register tiling for the 256x256.
// ---------------------------------------------------------------------------
__global__ __launch_bounds__(256) void adaat_params_kernel(
    const float* __restrict__ pc,
    const float* __restrict__ W1, const float* __restrict__ b1,
    const float* __restrict__ Ws, const float* __restrict__ bs,
    const float* __restrict__ Wr, const float* __restrict__ br,
    const float* __restrict__ Wt, const float* __restrict__ bt)
{
    const int b0  = blockIdx.x * ROWS;
    const int tid = threadIdx.x;

    __shared__ float pcs[PP][20];   // [k][r], padded row of 20 floats (80B, 16B-aligned slices)
    __shared__ float hs [PP][20];   // [k][r]

    // Load pc rows transposed into smem (coalesced global reads).
    for (int i = tid; i < ROWS * PP; i += 256) {
        int r = i >> 8;           // i / 256
        int k = i & (PP - 1);     // i % 256
        pcs[k][r] = pc[(size_t)(b0 + r) * PP + k];
    }
    __syncthreads();

    // Phase 1: 16x256 = rows x cols, thread tile 4x4.
    const int tr = tid >> 6;      // 0..3  -> rows tr*4 .. tr*4+3
    const int tc = tid & 63;      // 0..63 -> cols tc*4 .. tc*4+3

    float acc[4][4];
    {
        float4 bj = *(const float4*)(b1 + tc * 4);
        #pragma unroll
        for (int ri = 0; ri < 4; ri++) {
            acc[ri][0] = bj.x; acc[ri][1] = bj.y; acc[ri][2] = bj.z; acc[ri][3] = bj.w;
        }
    }
    #pragma unroll 4
    for (int k = 0; k < PP; k++) {
        float4 a = *(const float4*)(&pcs[k][tr * 4]);
        float4 w = *(const float4*)(W1 + (size_t)k * PP + tc * 4);
        float av[4] = {a.x, a.y, a.z, a.w};
        float wv[4] = {w.x, w.y, w.z, w.w};
        #pragma unroll
        for (int ri = 0; ri < 4; ri++)
            #pragma unroll
            for (int ci = 0; ci < 4; ci++)
                acc[ri][ci] = fmaf(av[ri], wv[ci], acc[ri][ci]);
    }
    // ReLU + store transposed: hs[k][r]
    #pragma unroll
    for (int ri = 0; ri < 4; ri++)
        #pragma unroll
        for (int ci = 0; ci < 4; ci++)
            hs[tc * 4 + ci][tr * 4 + ri] = fmaxf(acc[ri][ci], 0.f);
    __syncthreads();

    // Phase 2: per row r, 20 float4 output groups (og):
    //   og 0..4  -> scale (Ws, ld 20), og 5..9 -> angle (Wr, ld 20),
    //   og 10..19 -> trans (Wt, ld 40)
    for (int task = tid; task < ROWS * 20; task += 256) {
        int r  = task / 20;
        int og = task - r * 20;

        const float* Wm; const float* bm; int ld; int col;
        if (og < 5)        { Wm = Ws; bm = bs; ld = 20; col = og * 4; }
        else if (og < 10)  { Wm = Wr; bm = br; ld = 20; col = (og - 5) * 4; }
        else               { Wm = Wt; bm = bt; ld = 40; col = (og - 10) * 4; }

        float4 bb = *(const float4*)(bm + col);
        float o4[4] = {bb.x, bb.y, bb.z, bb.w};

        #pragma unroll 4
        for (int k = 0; k < PP; k++) {
            float  h = hs[k][r];
            float4 w = *(const float4*)(Wm + (size_t)k * ld + col);
            o4[0] = fmaf(h, w.x, o4[0]);
            o4[1] = fmaf(h, w.y, o4[1]);
            o4[2] = fmaf(h, w.z, o4[2]);
            o4[3] = fmaf(h, w.w, o4[3]);
        }

        float* pb = g_params + (size_t)(b0 + r) * FF * 5;
        if (og < 5) {
            #pragma unroll
            for (int ci = 0; ci < 4; ci++) {
                float sc = 2.f / (1.f + expf(-o4[ci]));
                pb[(og * 4 + ci) * 5 + 2] = sc;
            }
        } else if (og < 10) {
            #pragma unroll
            for (int ci = 0; ci < 4; ci++) {
                float ang = tanhf(o4[ci]) * PI_F;
                int f = (og - 5) * 4 + ci;
                pb[f * 5 + 0] = cosf(ang);
                pb[f * 5 + 1] = sinf(ang);
            }
        } else {
            #pragma unroll
            for (int ci = 0; ci < 4; ci++) {
                float t = tanhf(o4[ci]);
                int o = (og - 10) * 4 + ci;
                pb[(o >> 1) * 5 + 3 + (o & 1)] = t;
            }
        }
    }
}

// ---------------------------------------------------------------------------
// Kernel 2: per-batch trilinear grid sample. One CTA per batch element;
// the whole 20x18x18 volume lives in SMEM.
// ---------------------------------------------------------------------------
__global__ __launch_bounds__(256) void adaat_sample_kernel(
    const float* __restrict__ fm, float* __restrict__ out)
{
    const int b   = blockIdx.x;
    const int tid = threadIdx.x;

    __shared__ float vol[VOL];
    __shared__ float pc_c[FF], pc_s[FF], pc_sc[FF], pc_tx[FF], pc_ty[FF];
    __shared__ float pz_w0[FF], pz_w1[FF];
    __shared__ int   pz_z0[FF], pz_z1[FF];

    // Bulk-load the volume (VOL = 6480 floats = 1620 float4, 16B aligned).
    {
        const float4* src = (const float4*)(fm + (size_t)b * VOL);
        float4*       dst = (float4*)vol;
        for (int i = tid; i < VOL / 4; i += 256) dst[i] = src[i];
    }
    if (tid < FF) {
        const float* p = g_params + (size_t)(b * FF + tid) * 5;
        pc_c [tid] = p[0];
        pc_s [tid] = p[1];
        pc_sc[tid] = p[2];
        pc_tx[tid] = p[3];
        pc_ty[tid] = p[4];
        // z coordinate depends only on channel: z = 2f/(F-1) - 1
        float z   = 2.f * (float)tid / (float)(FF - 1) - 1.f;
        float iz  = ((z + 1.f) * (float)FF - 1.f) * 0.5f;
        float z0f = floorf(iz);
        float wz  = iz - z0f;
        int   z0  = (int)z0f;
        int   z1  = z0 + 1;
        pz_w0[tid] = (z0 >= 0 && z0 < FF) ? (1.f - wz) : 0.f;
        pz_w1[tid] = (z1 >= 0 && z1 < FF) ? wz         : 0.f;
        pz_z0[tid] = min(max(z0, 0), FF - 1);
        pz_z1[tid] = min(max(z1, 0), FF - 1);
    }
    __syncthreads();

    float* outb = out + (size_t)b * VOL;
    for (int i = tid; i < VOL; i += 256) {
        int f = i / HW;
        int p = i - f * HW;
        int y = p / WW;
        int x = p - y * WW;

        float gx = (float)x * (2.f / (float)(WW - 1)) - 1.f;
        float gy = (float)y * (2.f / (float)(HH - 1)) - 1.f;

        float c  = pc_c[f], s = pc_s[f], sc = pc_sc[f];
        float sx = fmaf(c, gx, -s * gy) * sc + pc_tx[f];
        float sy = fmaf(s, gx,  c * gy) * sc + pc_ty[f];

        float ix = ((sx + 1.f) * (float)WW - 1.f) * 0.5f;
        float iy = ((sy + 1.f) * (float)HH - 1.f) * 0.5f;

        float x0f = floorf(ix), y0f = floorf(iy);
        float wx  = ix - x0f,   wy  = iy - y0f;
        int   x0  = (int)x0f,   y0  = (int)y0f;
        int   x1  = x0 + 1,     y1  = y0 + 1;

        float wx0 = (x0 >= 0 && x0 < WW) ? (1.f - wx) : 0.f;
        float wx1 = (x1 >= 0 && x1 < WW) ? wx         : 0.f;
        float wy0 = (y0 >= 0 && y0 < HH) ? (1.f - wy) : 0.f;
        float wy1 = (y1 >= 0 && y1 < HH) ? wy         : 0.f;

        int x0c = min(max(x0, 0), WW - 1);
        int x1c = min(max(x1, 0), WW - 1);
        int y0c = min(max(y0, 0), HH - 1);
        int y1c = min(max(y1, 0), HH - 1);

        const float* v0 = vol + pz_z0[f] * HW;
        const float* v1 = vol + pz_z1[f] * HW;
        float w0 = pz_w0[f], w1 = pz_w1[f];

        float b00 = wx0 * wy0, b10 = wx1 * wy0;
        float b01 = wx0 * wy1, b11 = wx1 * wy1;

        int i00 = y0c * WW + x0c, i10 = y0c * WW + x1c;
        int i01 = y1c * WW + x0c, i11 = y1c * WW + x1c;

        float s0 = b00 * v0[i00] + b10 * v0[i10] + b01 * v0[i01] + b11 * v0[i11];
        float s1 = b00 * v1[i00] + b10 * v1[i10] + b01 * v1[i01] + b11 * v1[i11];

        outb[i] = w0 * s0 + w1 * s1;
    }
}

// ---------------------------------------------------------------------------
// Launch
// ---------------------------------------------------------------------------
extern "C" void kernel_launch(void* const* d_in, const int* in_sizes, int n_in,
                              void* d_out, int out_size)
{
    const float* feature_map = (const float*)d_in[0];
    const float* para_code   = (const float*)d_in[1];
    const float* W1          = (const float*)d_in[2];
    const float* b1          = (const float*)d_in[3];
    const float* Ws          = (const float*)d_in[4];
    const float* bs          = (const float*)d_in[5];
    const float* Wr          = (const float*)d_in[6];
    const float* br          = (const float*)d_in[7];
    const float* Wt          = (const float*)d_in[8];
    const float* bt          = (const float*)d_in[9];
    float*       out         = (float*)d_out;

    int B = in_sizes[1] / PP;   // para_code is (B, 256)
    if (B > MAXB) B = MAXB;

    adaat_params_kernel<<<B / ROWS, 256>>>(para_code, W1, b1, Ws, bs, Wr, br, Wt, bt);
    adaat_sample_kernel<<<B, 256>>>(feature_map, out);
}